// round 1
// baseline (speedup 1.0000x reference)
#include <cuda_runtime.h>
#include <cuda_bf16.h>
#include <math.h>

// Problem constants
#define BB 2
#define SS 2048
#define HH 2048
#define NHH 16
#define HDD 128
#define MROWS (BB * SS)   // 4096

// ---------------- scratch (no allocations allowed) ----------------
__device__ float g_Q[(size_t)MROWS * HH];
__device__ float g_K[(size_t)MROWS * HH];
__device__ float g_V[(size_t)MROWS * HH];
__device__ float g_C[(size_t)MROWS * HH];

// ---------------- GEMM: C = A[M,K] @ W[K,N] + bias[N] ----------------
// 128x128 tile, BK=8, 256 threads, 8x8 per thread.
__global__ __launch_bounds__(256) void gemm_bias_kernel(
    const float* __restrict__ A, const float* __restrict__ W,
    const float* __restrict__ bias, float* __restrict__ C,
    int M, int N, int K)
{
    __shared__ float As[8][128];
    __shared__ float Bs[8][128];

    const int tid = threadIdx.x;
    const int tx = tid & 15;
    const int ty = tid >> 4;
    const int bm = blockIdx.y * 128;
    const int bn = blockIdx.x * 128;

    const int a_row = tid >> 1;          // 0..127
    const int a_k4  = (tid & 1) * 4;     // 0 or 4
    const int b_k   = tid >> 5;          // 0..7
    const int b_c4  = (tid & 31) * 4;    // 0..124

    float acc[8][8];
#pragma unroll
    for (int i = 0; i < 8; i++)
#pragma unroll
        for (int j = 0; j < 8; j++) acc[i][j] = 0.f;

    const float* Aptr = A + (size_t)(bm + a_row) * K + a_k4;
    const float* Wptr = W + (size_t)b_k * N + bn + b_c4;

    for (int k0 = 0; k0 < K; k0 += 8) {
        float4 av = *(const float4*)(Aptr + k0);
        float4 wv = *(const float4*)(Wptr + (size_t)k0 * N);
        As[a_k4 + 0][a_row] = av.x;
        As[a_k4 + 1][a_row] = av.y;
        As[a_k4 + 2][a_row] = av.z;
        As[a_k4 + 3][a_row] = av.w;
        *(float4*)&Bs[b_k][b_c4] = wv;
        __syncthreads();

#pragma unroll
        for (int kk = 0; kk < 8; kk++) {
            float4 a0 = *(const float4*)&As[kk][ty * 8];
            float4 a1 = *(const float4*)&As[kk][ty * 8 + 4];
            float4 b0 = *(const float4*)&Bs[kk][tx * 8];
            float4 b1 = *(const float4*)&Bs[kk][tx * 8 + 4];
            float a_[8] = {a0.x, a0.y, a0.z, a0.w, a1.x, a1.y, a1.z, a1.w};
            float b_[8] = {b0.x, b0.y, b0.z, b0.w, b1.x, b1.y, b1.z, b1.w};
#pragma unroll
            for (int i = 0; i < 8; i++)
#pragma unroll
                for (int j = 0; j < 8; j++)
                    acc[i][j] = fmaf(a_[i], b_[j], acc[i][j]);
        }
        __syncthreads();
    }

    // epilogue with bias
    float bvals[8];
#pragma unroll
    for (int j = 0; j < 8; j++) bvals[j] = bias[bn + tx * 8 + j];

#pragma unroll
    for (int i = 0; i < 8; i++) {
        const int row = bm + ty * 8 + i;
        float4 r0, r1;
        r0.x = acc[i][0] + bvals[0];
        r0.y = acc[i][1] + bvals[1];
        r0.z = acc[i][2] + bvals[2];
        r0.w = acc[i][3] + bvals[3];
        r1.x = acc[i][4] + bvals[4];
        r1.y = acc[i][5] + bvals[5];
        r1.z = acc[i][6] + bvals[6];
        r1.w = acc[i][7] + bvals[7];
        *(float4*)&C[(size_t)row * N + bn + tx * 8]     = r0;
        *(float4*)&C[(size_t)row * N + bn + tx * 8 + 4] = r1;
    }
}

// ---------------- Flash attention (fp32, online softmax) ----------------
// Grid: (S/64, NH, B). Block: 256 threads (16x16).
// Each block: 64 q-rows x 128 head-dim, streaming 64-key tiles.
#define FL_QS_ELEMS (64 * 128)
#define FL_KT_ELEMS (128 * 65)     // K transposed, pad 65 to break conflicts
#define FL_VS_ELEMS (64 * 128)
#define FL_PS_ELEMS (64 * 68)      // P tile, pad 68
#define FL_SMEM_BYTES ((FL_QS_ELEMS + FL_KT_ELEMS + FL_VS_ELEMS + FL_PS_ELEMS) * 4)

__global__ __launch_bounds__(256) void flash_kernel(
    const float* __restrict__ Q, const float* __restrict__ K,
    const float* __restrict__ V, const float* __restrict__ mask,
    float* __restrict__ Ctx, int S)
{
    extern __shared__ float sm[];
    float* Qs  = sm;                       // [64][128]
    float* Kst = Qs + FL_QS_ELEMS;         // [128][65]  (Kst[k][key])
    float* Vs  = Kst + FL_KT_ELEMS;        // [64][128]
    float* Ps  = Vs + FL_VS_ELEMS;         // [64][68]

    const int Hdim = HH;
    const int b = blockIdx.z;
    const int h = blockIdx.y;
    const int q0 = blockIdx.x * 64;
    const int tid = threadIdx.x;
    const int tx = tid & 15;
    const int ty = tid >> 4;
    const float scale = 0.08838834764831845f;  // 1/sqrt(128)

    const size_t base = (size_t)b * S * Hdim + (size_t)h * HDD;

    // load Q tile (64 rows x 128)
#pragma unroll
    for (int i = tid; i < 64 * 32; i += 256) {
        int r = i >> 5;
        int c4 = (i & 31) << 2;
        *(float4*)&Qs[r * 128 + c4] =
            *(const float4*)&Q[base + (size_t)(q0 + r) * Hdim + c4];
    }

    float m_i[4], l_i[4], o[4][8];
#pragma unroll
    for (int i = 0; i < 4; i++) {
        m_i[i] = -1e30f;
        l_i[i] = 0.f;
#pragma unroll
        for (int c = 0; c < 8; c++) o[i][c] = 0.f;
    }
    __syncthreads();

    const float* mrow_base = mask + (size_t)b * S;

    for (int kt = 0; kt < S / 64; kt++) {
        const int k0 = kt * 64;
        // load K (transposed into Kst) and V
#pragma unroll
        for (int i = tid; i < 64 * 32; i += 256) {
            int r = i >> 5;
            int c4 = (i & 31) << 2;
            float4 kv = *(const float4*)&K[base + (size_t)(k0 + r) * Hdim + c4];
            Kst[(c4 + 0) * 65 + r] = kv.x;
            Kst[(c4 + 1) * 65 + r] = kv.y;
            Kst[(c4 + 2) * 65 + r] = kv.z;
            Kst[(c4 + 3) * 65 + r] = kv.w;
            *(float4*)&Vs[r * 128 + c4] =
                *(const float4*)&V[base + (size_t)(k0 + r) * Hdim + c4];
        }
        __syncthreads();

        // S = Q K^T   (4x4 per thread)
        float s[4][4];
#pragma unroll
        for (int i = 0; i < 4; i++)
#pragma unroll
            for (int j = 0; j < 4; j++) s[i][j] = 0.f;

#pragma unroll 8
        for (int k = 0; k < HDD; k++) {
            float qv[4], kv[4];
#pragma unroll
            for (int i = 0; i < 4; i++) qv[i] = Qs[(ty * 4 + i) * 128 + k];
#pragma unroll
            for (int j = 0; j < 4; j++) kv[j] = Kst[k * 65 + tx * 4 + j];
#pragma unroll
            for (int i = 0; i < 4; i++)
#pragma unroll
                for (int j = 0; j < 4; j++)
                    s[i][j] = fmaf(qv[i], kv[j], s[i][j]);
        }

        // scale + mask
        float mk[4];
#pragma unroll
        for (int j = 0; j < 4; j++) mk[j] = mrow_base[k0 + tx * 4 + j];
#pragma unroll
        for (int i = 0; i < 4; i++)
#pragma unroll
            for (int j = 0; j < 4; j++)
                s[i][j] = fmaf(s[i][j], scale, mk[j]);

        // online softmax per row (reduce across tx, 16-lane segments)
#pragma unroll
        for (int i = 0; i < 4; i++) {
            float rm = fmaxf(fmaxf(s[i][0], s[i][1]), fmaxf(s[i][2], s[i][3]));
#pragma unroll
            for (int off = 8; off > 0; off >>= 1)
                rm = fmaxf(rm, __shfl_xor_sync(0xffffffffu, rm, off, 16));
            float nm = fmaxf(m_i[i], rm);
            float corr = __expf(m_i[i] - nm);
            float rsum = 0.f;
#pragma unroll
            for (int j = 0; j < 4; j++) {
                s[i][j] = __expf(s[i][j] - nm);
                rsum += s[i][j];
            }
#pragma unroll
            for (int off = 8; off > 0; off >>= 1)
                rsum += __shfl_xor_sync(0xffffffffu, rsum, off, 16);
            l_i[i] = l_i[i] * corr + rsum;
            m_i[i] = nm;
#pragma unroll
            for (int c = 0; c < 8; c++) o[i][c] *= corr;
            // stage P (same-warp producer/consumer)
            float4 pv = make_float4(s[i][0], s[i][1], s[i][2], s[i][3]);
            *(float4*)&Ps[(ty * 4 + i) * 68 + tx * 4] = pv;
        }
        __syncwarp();

        // O += P @ V    (4 rows x 8 out-cols per thread)
#pragma unroll 4
        for (int j = 0; j < 64; j++) {
            float4 v0 = *(const float4*)&Vs[j * 128 + tx * 8];
            float4 v1 = *(const float4*)&Vs[j * 128 + tx * 8 + 4];
#pragma unroll
            for (int i = 0; i < 4; i++) {
                float p = Ps[(ty * 4 + i) * 68 + j];
                o[i][0] = fmaf(p, v0.x, o[i][0]);
                o[i][1] = fmaf(p, v0.y, o[i][1]);
                o[i][2] = fmaf(p, v0.z, o[i][2]);
                o[i][3] = fmaf(p, v0.w, o[i][3]);
                o[i][4] = fmaf(p, v1.x, o[i][4]);
                o[i][5] = fmaf(p, v1.y, o[i][5]);
                o[i][6] = fmaf(p, v1.z, o[i][6]);
                o[i][7] = fmaf(p, v1.w, o[i][7]);
            }
        }
        __syncthreads();   // before next tile overwrites Kst/Vs
    }

    // write context
#pragma unroll
    for (int i = 0; i < 4; i++) {
        const float inv = 1.f / l_i[i];
        const int row = q0 + ty * 4 + i;
        float4 r0, r1;
        r0.x = o[i][0] * inv; r0.y = o[i][1] * inv;
        r0.z = o[i][2] * inv; r0.w = o[i][3] * inv;
        r1.x = o[i][4] * inv; r1.y = o[i][5] * inv;
        r1.z = o[i][6] * inv; r1.w = o[i][7] * inv;
        *(float4*)&Ctx[base + (size_t)row * Hdim + tx * 8]     = r0;
        *(float4*)&Ctx[base + (size_t)row * Hdim + tx * 8 + 4] = r1;
    }
}

// ---------------- launch ----------------
extern "C" void kernel_launch(void* const* d_in, const int* in_sizes, int n_in,
                              void* d_out, int out_size)
{
    (void)in_sizes; (void)n_in; (void)out_size;
    const float* x    = (const float*)d_in[0];
    const float* mask = (const float*)d_in[1];
    const float* Wq   = (const float*)d_in[2];
    const float* bq   = (const float*)d_in[3];
    const float* Wk   = (const float*)d_in[4];
    const float* bk   = (const float*)d_in[5];
    const float* Wv   = (const float*)d_in[6];
    const float* bv   = (const float*)d_in[7];
    const float* Wo   = (const float*)d_in[8];
    const float* bo   = (const float*)d_in[9];
    float* out = (float*)d_out;

    float *Qp, *Kp, *Vp, *Cp;
    cudaGetSymbolAddress((void**)&Qp, g_Q);
    cudaGetSymbolAddress((void**)&Kp, g_K);
    cudaGetSymbolAddress((void**)&Vp, g_V);
    cudaGetSymbolAddress((void**)&Cp, g_C);

    dim3 gemm_grid(HH / 128, MROWS / 128);
    gemm_bias_kernel<<<gemm_grid, 256>>>(x, Wq, bq, Qp, MROWS, HH, HH);
    gemm_bias_kernel<<<gemm_grid, 256>>>(x, Wk, bk, Kp, MROWS, HH, HH);
    gemm_bias_kernel<<<gemm_grid, 256>>>(x, Wv, bv, Vp, MROWS, HH, HH);

    cudaFuncSetAttribute(flash_kernel,
                         cudaFuncAttributeMaxDynamicSharedMemorySize,
                         FL_SMEM_BYTES);
    flash_kernel<<<dim3(SS / 64, NHH, BB), 256, FL_SMEM_BYTES>>>(
        Qp, Kp, Vp, mask, Cp, SS);

    gemm_bias_kernel<<<gemm_grid, 256>>>(Cp, Wo, bo, out, MROWS, HH, HH);
}

// round 3
// speedup vs baseline: 1.5158x; 1.5158x over previous
#include <cuda_runtime.h>
#include <cuda_bf16.h>
#include <math.h>
#include <stdint.h>

// Problem constants
#define BB 2
#define SS 2048
#define HH 2048
#define NHH 16
#define HDD 128
#define MROWS (BB * SS)   // 4096

// ---------------- scratch (no allocations allowed) ----------------
__device__ float g_Q[(size_t)MROWS * HH];
__device__ float g_K[(size_t)MROWS * HH];
__device__ float g_V[(size_t)MROWS * HH];
__device__ float g_C[(size_t)MROWS * HH];
__device__ __nv_bfloat16 g_xhi[(size_t)MROWS * HH];
__device__ __nv_bfloat16 g_xlo[(size_t)MROWS * HH];
__device__ __nv_bfloat16 g_wthi[(size_t)HH * HH];
__device__ __nv_bfloat16 g_wtlo[(size_t)HH * HH];

// ================= PTX helpers (baseline ISA only, no 'a' features) ===========
__device__ __forceinline__ uint32_t smem_u32(const void* p) {
    uint32_t a;
    asm("{ .reg .u64 t; cvta.to.shared.u64 t, %1; cvt.u32.u64 %0, t; }"
        : "=r"(a) : "l"(p));
    return a;
}

__device__ __forceinline__ void cp_async16(uint32_t smem, const void* g) {
    asm volatile("cp.async.cg.shared.global [%0], [%1], 16;"
                 :: "r"(smem), "l"(g) : "memory");
}
#define CP_COMMIT() asm volatile("cp.async.commit_group;" ::: "memory")
template <int N>
__device__ __forceinline__ void cp_wait() {
    asm volatile("cp.async.wait_group %0;" :: "n"(N) : "memory");
}

__device__ __forceinline__ void ldmat_x4(uint32_t* r, uint32_t addr) {
    asm volatile("ldmatrix.sync.aligned.m8n8.x4.shared.b16 {%0,%1,%2,%3}, [%4];"
                 : "=r"(r[0]), "=r"(r[1]), "=r"(r[2]), "=r"(r[3]) : "r"(addr));
}

__device__ __forceinline__ void mma_bf16(float* d, const uint32_t* a, const uint32_t* b) {
    asm volatile(
        "mma.sync.aligned.m16n8k16.row.col.f32.bf16.bf16.f32 "
        "{%0,%1,%2,%3}, {%4,%5,%6,%7}, {%8,%9}, {%0,%1,%2,%3};"
        : "+f"(d[0]), "+f"(d[1]), "+f"(d[2]), "+f"(d[3])
        : "r"(a[0]), "r"(a[1]), "r"(a[2]), "r"(a[3]), "r"(b[0]), "r"(b[1]));
}

// ================= bf16-split GEMM via mma.sync =================
// C[M,N] = A[M,K] @ Bt[N,K]^T + bias.  A/Bt given as (hi,lo) bf16 pairs.
// Tile 128x128x32, 256 threads (8 warps as 2(m) x 4(n)), warp tile 64x32.
#define G_BM 128
#define G_BN 128
#define G_BK 32
#define G_PAD 40                         // bf16 elems per smem row (32 + 8 pad)
#define G_ARR_ELEMS (128 * G_PAD)        // per array per stage
#define G_ARR_BYTES (G_ARR_ELEMS * 2)    // 10240 B
#define G_STAGE_BYTES (4 * G_ARR_BYTES)  // Ahi,Alo,Bhi,Blo = 40960 B
#define G_SMEM_BYTES (2 * G_STAGE_BYTES) // 81920 B

__global__ __launch_bounds__(256, 1)
void gemm_tc_kernel(const __nv_bfloat16* __restrict__ Ahi,
                    const __nv_bfloat16* __restrict__ Alo,
                    const __nv_bfloat16* __restrict__ Bhi,
                    const __nv_bfloat16* __restrict__ Blo,
                    const float* __restrict__ bias,
                    float* __restrict__ C,
                    int Kd, int Nd)
{
    extern __shared__ __align__(128) unsigned char dynsm[];
    const int tid = threadIdx.x;
    const int wid = tid >> 5;
    const int lane = tid & 31;
    const int wm = wid & 1;        // 0..1  (m)
    const int wn = wid >> 1;       // 0..3  (n)
    const int bm = blockIdx.y * G_BM;
    const int bn = blockIdx.x * G_BN;
    const int NK = Kd / G_BK;

    const uint32_t smem_base = smem_u32(dynsm);

    // ---- async tile loader: 4 arrays x 512 chunks of 16B ----
    auto load_stage = [&](int st, int kt) {
        const int k0 = kt * G_BK;
        const uint32_t sb = smem_base + st * G_STAGE_BYTES;
#pragma unroll
        for (int i = tid; i < 2048; i += 256) {
            const int arr = i >> 9;       // 0 Ahi, 1 Alo, 2 Bhi, 3 Blo
            const int t = i & 511;
            const int r = t >> 2;         // 0..127
            const int c = t & 3;          // 16B chunk (8 bf16)
            const uint32_t soff = sb + arr * G_ARR_BYTES + r * (G_PAD * 2) + c * 16;
            const __nv_bfloat16* g;
            if (arr == 0)      g = Ahi + (size_t)(bm + r) * Kd + k0 + c * 8;
            else if (arr == 1) g = Alo + (size_t)(bm + r) * Kd + k0 + c * 8;
            else if (arr == 2) g = Bhi + (size_t)(bn + r) * Kd + k0 + c * 8;
            else               g = Blo + (size_t)(bn + r) * Kd + k0 + c * 8;
            cp_async16(soff, g);
        }
        CP_COMMIT();
    };

    float acc[4][4][4];
#pragma unroll
    for (int i = 0; i < 4; i++)
#pragma unroll
        for (int j = 0; j < 4; j++)
#pragma unroll
            for (int c = 0; c < 4; c++) acc[i][j][c] = 0.f;

    // ldmatrix lane addressing (byte offsets within an array)
    // A: row = warp_m_base + mtile*16 + (lane&15), col k = kk + (lane>>4)*8
    const int a_row_l = (lane & 15);
    const int a_k_l = (lane >> 4) * 8;
    // B: row n = warp_n_base + (lane&7) + (lane>>4)*8, col k = kk + ((lane>>3)&1)*8
    const int b_row_l = (lane & 7) + (lane >> 4) * 8;
    const int b_k_l = ((lane >> 3) & 1) * 8;

    load_stage(0, 0);

    for (int kt = 0; kt < NK; kt++) {
        if (kt + 1 < NK) load_stage((kt + 1) & 1, kt + 1);
        else CP_COMMIT();                 // empty group so wait<1> drains stage kt
        cp_wait<1>();
        __syncthreads();

        const uint32_t sb = smem_base + (kt & 1) * G_STAGE_BYTES;
        const uint32_t aHiB = sb + 0 * G_ARR_BYTES;
        const uint32_t aLoB = sb + 1 * G_ARR_BYTES;
        const uint32_t bHiB = sb + 2 * G_ARR_BYTES;
        const uint32_t bLoB = sb + 3 * G_ARR_BYTES;

#pragma unroll
        for (int ks = 0; ks < 2; ks++) {          // two k16 steps
            const int kk = ks * 16;
            uint32_t ah[4][4], al[4][4], bh[2][4], bl[2][4];
#pragma unroll
            for (int i = 0; i < 4; i++) {         // 4 m16 tiles (warp m64)
                const int row = wm * 64 + i * 16 + a_row_l;
                const uint32_t off = row * (G_PAD * 2) + (kk + a_k_l) * 2;
                ldmat_x4(ah[i], aHiB + off);
                ldmat_x4(al[i], aLoB + off);
            }
#pragma unroll
            for (int j = 0; j < 2; j++) {         // 2 x4 loads cover 4 n8 tiles
                const int nrow = wn * 32 + j * 16 + b_row_l;
                const uint32_t off = nrow * (G_PAD * 2) + (kk + b_k_l) * 2;
                ldmat_x4(bh[j], bHiB + off);
                ldmat_x4(bl[j], bLoB + off);
            }
#pragma unroll
            for (int i = 0; i < 4; i++)
#pragma unroll
                for (int j = 0; j < 4; j++) {
                    const uint32_t* bfh = &bh[j >> 1][(j & 1) * 2];
                    const uint32_t* bfl = &bl[j >> 1][(j & 1) * 2];
                    mma_bf16(acc[i][j], ah[i], bfh);
                    mma_bf16(acc[i][j], ah[i], bfl);
                    mma_bf16(acc[i][j], al[i], bfh);
                }
        }
        __syncthreads();
    }

    // ---- epilogue: bias + store ----
    const int qid = lane >> 2;     // 0..7
    const int tq = lane & 3;       // 0..3
#pragma unroll
    for (int j = 0; j < 4; j++) {
        const int col = bn + wn * 32 + j * 8 + tq * 2;
        const float b0 = __ldg(&bias[col]);
        const float b1 = __ldg(&bias[col + 1]);
#pragma unroll
        for (int i = 0; i < 4; i++) {
            const int r0 = bm + wm * 64 + i * 16 + qid;
            float2 v0 = make_float2(acc[i][j][0] + b0, acc[i][j][1] + b1);
            float2 v1 = make_float2(acc[i][j][2] + b0, acc[i][j][3] + b1);
            *(float2*)&C[(size_t)r0 * Nd + col] = v0;
            *(float2*)&C[(size_t)(r0 + 8) * Nd + col] = v1;
        }
    }
}

// ================= conversion kernels =================
__global__ __launch_bounds__(256) void split_kernel(
    const float* __restrict__ in, __nv_bfloat16* __restrict__ hi,
    __nv_bfloat16* __restrict__ lo, int n4)
{
    int i = blockIdx.x * blockDim.x + threadIdx.x;
    if (i >= n4) return;
    float4 v = ((const float4*)in)[i];
    __nv_bfloat16 h0 = __float2bfloat16_rn(v.x);
    __nv_bfloat16 h1 = __float2bfloat16_rn(v.y);
    __nv_bfloat16 h2 = __float2bfloat16_rn(v.z);
    __nv_bfloat16 h3 = __float2bfloat16_rn(v.w);
    __nv_bfloat16 l0 = __float2bfloat16_rn(v.x - __bfloat162float(h0));
    __nv_bfloat16 l1 = __float2bfloat16_rn(v.y - __bfloat162float(h1));
    __nv_bfloat16 l2 = __float2bfloat16_rn(v.z - __bfloat162float(h2));
    __nv_bfloat16 l3 = __float2bfloat16_rn(v.w - __bfloat162float(h3));
    ((__nv_bfloat162*)hi)[i * 2 + 0] = __halves2bfloat162(h0, h1);
    ((__nv_bfloat162*)hi)[i * 2 + 1] = __halves2bfloat162(h2, h3);
    ((__nv_bfloat162*)lo)[i * 2 + 0] = __halves2bfloat162(l0, l1);
    ((__nv_bfloat162*)lo)[i * 2 + 1] = __halves2bfloat162(l2, l3);
}

// W[K][N] fp32 -> Wt_hi/lo[N][K] bf16  (32x32 tiles)
__global__ __launch_bounds__(256) void transpose_split_kernel(
    const float* __restrict__ W, __nv_bfloat16* __restrict__ Th,
    __nv_bfloat16* __restrict__ Tl, int Kd, int Nd)
{
    __shared__ float t[32][33];
    const int k0 = blockIdx.y * 32;
    const int n0 = blockIdx.x * 32;
    const int tx = threadIdx.x;
    const int ty = threadIdx.y;
#pragma unroll
    for (int j = 0; j < 4; j++)
        t[ty + j * 8][tx] = W[(size_t)(k0 + ty + j * 8) * Nd + n0 + tx];
    __syncthreads();
#pragma unroll
    for (int j = 0; j < 4; j++) {
        int n = n0 + ty + j * 8;
        int k = k0 + tx;
        float v = t[tx][ty + j * 8];
        __nv_bfloat16 h = __float2bfloat16_rn(v);
        __nv_bfloat16 l = __float2bfloat16_rn(v - __bfloat162float(h));
        Th[(size_t)n * Kd + k] = h;
        Tl[(size_t)n * Kd + k] = l;
    }
}

// ---------------- Flash attention (fp32, online softmax) ----------------
#define FL_QS_ELEMS (64 * 128)
#define FL_KT_ELEMS (128 * 65)
#define FL_VS_ELEMS (64 * 128)
#define FL_PS_ELEMS (64 * 68)
#define FL_SMEM_BYTES ((FL_QS_ELEMS + FL_KT_ELEMS + FL_VS_ELEMS + FL_PS_ELEMS) * 4)

__global__ __launch_bounds__(256) void flash_kernel(
    const float* __restrict__ Q, const float* __restrict__ K,
    const float* __restrict__ V, const float* __restrict__ mask,
    float* __restrict__ Ctx, int S)
{
    extern __shared__ float sm[];
    float* Qs  = sm;
    float* Kst = Qs + FL_QS_ELEMS;
    float* Vs  = Kst + FL_KT_ELEMS;
    float* Ps  = Vs + FL_VS_ELEMS;

    const int Hdim = HH;
    const int b = blockIdx.z;
    const int h = blockIdx.y;
    const int q0 = blockIdx.x * 64;
    const int tid = threadIdx.x;
    const int tx = tid & 15;
    const int ty = tid >> 4;
    const float scale = 0.08838834764831845f;

    const size_t base = (size_t)b * S * Hdim + (size_t)h * HDD;

#pragma unroll
    for (int i = tid; i < 64 * 32; i += 256) {
        int r = i >> 5;
        int c4 = (i & 31) << 2;
        *(float4*)&Qs[r * 128 + c4] =
            *(const float4*)&Q[base + (size_t)(q0 + r) * Hdim + c4];
    }

    float m_i[4], l_i[4], o[4][8];
#pragma unroll
    for (int i = 0; i < 4; i++) {
        m_i[i] = -1e30f;
        l_i[i] = 0.f;
#pragma unroll
        for (int c = 0; c < 8; c++) o[i][c] = 0.f;
    }
    __syncthreads();

    const float* mrow_base = mask + (size_t)b * S;

    for (int kt = 0; kt < S / 64; kt++) {
        const int k0 = kt * 64;
#pragma unroll
        for (int i = tid; i < 64 * 32; i += 256) {
            int r = i >> 5;
            int c4 = (i & 31) << 2;
            float4 kv = *(const float4*)&K[base + (size_t)(k0 + r) * Hdim + c4];
            Kst[(c4 + 0) * 65 + r] = kv.x;
            Kst[(c4 + 1) * 65 + r] = kv.y;
            Kst[(c4 + 2) * 65 + r] = kv.z;
            Kst[(c4 + 3) * 65 + r] = kv.w;
            *(float4*)&Vs[r * 128 + c4] =
                *(const float4*)&V[base + (size_t)(k0 + r) * Hdim + c4];
        }
        __syncthreads();

        float s[4][4];
#pragma unroll
        for (int i = 0; i < 4; i++)
#pragma unroll
            for (int j = 0; j < 4; j++) s[i][j] = 0.f;

#pragma unroll 8
        for (int k = 0; k < HDD; k++) {
            float qv[4], kv[4];
#pragma unroll
            for (int i = 0; i < 4; i++) qv[i] = Qs[(ty * 4 + i) * 128 + k];
#pragma unroll
            for (int j = 0; j < 4; j++) kv[j] = Kst[k * 65 + tx * 4 + j];
#pragma unroll
            for (int i = 0; i < 4; i++)
#pragma unroll
                for (int j = 0; j < 4; j++)
                    s[i][j] = fmaf(qv[i], kv[j], s[i][j]);
        }

        float mk[4];
#pragma unroll
        for (int j = 0; j < 4; j++) mk[j] = mrow_base[k0 + tx * 4 + j];
#pragma unroll
        for (int i = 0; i < 4; i++)
#pragma unroll
            for (int j = 0; j < 4; j++)
                s[i][j] = fmaf(s[i][j], scale, mk[j]);

#pragma unroll
        for (int i = 0; i < 4; i++) {
            float rm = fmaxf(fmaxf(s[i][0], s[i][1]), fmaxf(s[i][2], s[i][3]));
#pragma unroll
            for (int off = 8; off > 0; off >>= 1)
                rm = fmaxf(rm, __shfl_xor_sync(0xffffffffu, rm, off, 16));
            float nm = fmaxf(m_i[i], rm);
            float corr = __expf(m_i[i] - nm);
            float rsum = 0.f;
#pragma unroll
            for (int j = 0; j < 4; j++) {
                s[i][j] = __expf(s[i][j] - nm);
                rsum += s[i][j];
            }
#pragma unroll
            for (int off = 8; off > 0; off >>= 1)
                rsum += __shfl_xor_sync(0xffffffffu, rsum, off, 16);
            l_i[i] = l_i[i] * corr + rsum;
            m_i[i] = nm;
#pragma unroll
            for (int c = 0; c < 8; c++) o[i][c] *= corr;
            float4 pv = make_float4(s[i][0], s[i][1], s[i][2], s[i][3]);
            *(float4*)&Ps[(ty * 4 + i) * 68 + tx * 4] = pv;
        }
        __syncwarp();

#pragma unroll 4
        for (int j = 0; j < 64; j++) {
            float4 v0 = *(const float4*)&Vs[j * 128 + tx * 8];
            float4 v1 = *(const float4*)&Vs[j * 128 + tx * 8 + 4];
#pragma unroll
            for (int i = 0; i < 4; i++) {
                float p = Ps[(ty * 4 + i) * 68 + j];
                o[i][0] = fmaf(p, v0.x, o[i][0]);
                o[i][1] = fmaf(p, v0.y, o[i][1]);
                o[i][2] = fmaf(p, v0.z, o[i][2]);
                o[i][3] = fmaf(p, v0.w, o[i][3]);
                o[i][4] = fmaf(p, v1.x, o[i][4]);
                o[i][5] = fmaf(p, v1.y, o[i][5]);
                o[i][6] = fmaf(p, v1.z, o[i][6]);
                o[i][7] = fmaf(p, v1.w, o[i][7]);
            }
        }
        __syncthreads();
    }

#pragma unroll
    for (int i = 0; i < 4; i++) {
        const float inv = 1.f / l_i[i];
        const int row = q0 + ty * 4 + i;
        float4 r0, r1;
        r0.x = o[i][0] * inv; r0.y = o[i][1] * inv;
        r0.z = o[i][2] * inv; r0.w = o[i][3] * inv;
        r1.x = o[i][4] * inv; r1.y = o[i][5] * inv;
        r1.z = o[i][6] * inv; r1.w = o[i][7] * inv;
        *(float4*)&Ctx[base + (size_t)row * Hdim + tx * 8]     = r0;
        *(float4*)&Ctx[base + (size_t)row * Hdim + tx * 8 + 4] = r1;
    }
}

// ---------------- launch ----------------
extern "C" void kernel_launch(void* const* d_in, const int* in_sizes, int n_in,
                              void* d_out, int out_size)
{
    (void)in_sizes; (void)n_in; (void)out_size;
    const float* x    = (const float*)d_in[0];
    const float* mask = (const float*)d_in[1];
    const float* Wq   = (const float*)d_in[2];
    const float* bq   = (const float*)d_in[3];
    const float* Wk   = (const float*)d_in[4];
    const float* bk   = (const float*)d_in[5];
    const float* Wv   = (const float*)d_in[6];
    const float* bv   = (const float*)d_in[7];
    const float* Wo   = (const float*)d_in[8];
    const float* bo   = (const float*)d_in[9];
    float* out = (float*)d_out;

    float *Qp, *Kp, *Vp, *Cp;
    __nv_bfloat16 *xhi, *xlo, *wthi, *wtlo;
    cudaGetSymbolAddress((void**)&Qp, g_Q);
    cudaGetSymbolAddress((void**)&Kp, g_K);
    cudaGetSymbolAddress((void**)&Vp, g_V);
    cudaGetSymbolAddress((void**)&Cp, g_C);
    cudaGetSymbolAddress((void**)&xhi, g_xhi);
    cudaGetSymbolAddress((void**)&xlo, g_xlo);
    cudaGetSymbolAddress((void**)&wthi, g_wthi);
    cudaGetSymbolAddress((void**)&wtlo, g_wtlo);

    cudaFuncSetAttribute(gemm_tc_kernel,
                         cudaFuncAttributeMaxDynamicSharedMemorySize, G_SMEM_BYTES);
    cudaFuncSetAttribute(flash_kernel,
                         cudaFuncAttributeMaxDynamicSharedMemorySize, FL_SMEM_BYTES);

    const int n4 = (MROWS * HH) / 4;
    dim3 tgrid(HH / 32, HH / 32);
    dim3 tblk(32, 8);
    dim3 ggrid(HH / G_BN, MROWS / G_BM);

    // split x once
    split_kernel<<<(n4 + 255) / 256, 256>>>(x, xhi, xlo, n4);

    // Q, K, V projections
    transpose_split_kernel<<<tgrid, tblk>>>(Wq, wthi, wtlo, HH, HH);
    gemm_tc_kernel<<<ggrid, 256, G_SMEM_BYTES>>>(xhi, xlo, wthi, wtlo, bq, Qp, HH, HH);
    transpose_split_kernel<<<tgrid, tblk>>>(Wk, wthi, wtlo, HH, HH);
    gemm_tc_kernel<<<ggrid, 256, G_SMEM_BYTES>>>(xhi, xlo, wthi, wtlo, bk, Kp, HH, HH);
    transpose_split_kernel<<<tgrid, tblk>>>(Wv, wthi, wtlo, HH, HH);
    gemm_tc_kernel<<<ggrid, 256, G_SMEM_BYTES>>>(xhi, xlo, wthi, wtlo, bv, Vp, HH, HH);

    // attention
    flash_kernel<<<dim3(SS / 64, NHH, BB), 256, FL_SMEM_BYTES>>>(
        Qp, Kp, Vp, mask, Cp, SS);

    // output projection
    split_kernel<<<(n4 + 255) / 256, 256>>>(Cp, xhi, xlo, n4);
    transpose_split_kernel<<<tgrid, tblk>>>(Wo, wthi, wtlo, HH, HH);
    gemm_tc_kernel<<<ggrid, 256, G_SMEM_BYTES>>>(xhi, xlo, wthi, wtlo, bo, out, HH, HH);
}

// round 4
// speedup vs baseline: 2.8100x; 1.8538x over previous
#include <cuda_runtime.h>
#include <cuda_bf16.h>
#include <math.h>
#include <stdint.h>

// Problem constants
#define BB 2
#define SS 2048
#define HH 2048
#define NHH 16
#define HDD 128
#define MROWS (BB * SS)   // 4096

// ---------------- scratch (no allocations allowed) ----------------
__device__ __nv_bfloat16 g_Qhi[(size_t)MROWS * HH];
__device__ __nv_bfloat16 g_Qlo[(size_t)MROWS * HH];
__device__ __nv_bfloat16 g_Khi[(size_t)MROWS * HH];
__device__ __nv_bfloat16 g_Klo[(size_t)MROWS * HH];
__device__ __nv_bfloat16 g_Vhi[(size_t)MROWS * HH];
__device__ __nv_bfloat16 g_Vlo[(size_t)MROWS * HH];
__device__ __nv_bfloat16 g_xhi[(size_t)MROWS * HH];
__device__ __nv_bfloat16 g_xlo[(size_t)MROWS * HH];
__device__ __nv_bfloat16 g_wthi[(size_t)HH * HH];
__device__ __nv_bfloat16 g_wtlo[(size_t)HH * HH];

// ================= PTX helpers (baseline ISA only) ===========
__device__ __forceinline__ uint32_t smem_u32(const void* p) {
    uint32_t a;
    asm("{ .reg .u64 t; cvta.to.shared.u64 t, %1; cvt.u32.u64 %0, t; }"
        : "=r"(a) : "l"(p));
    return a;
}

__device__ __forceinline__ void cp_async16(uint32_t smem, const void* g) {
    asm volatile("cp.async.cg.shared.global [%0], [%1], 16;"
                 :: "r"(smem), "l"(g) : "memory");
}
#define CP_COMMIT() asm volatile("cp.async.commit_group;" ::: "memory")
template <int N>
__device__ __forceinline__ void cp_wait() {
    asm volatile("cp.async.wait_group %0;" :: "n"(N) : "memory");
}

__device__ __forceinline__ void ldmat_x4(uint32_t* r, uint32_t addr) {
    asm volatile("ldmatrix.sync.aligned.m8n8.x4.shared.b16 {%0,%1,%2,%3}, [%4];"
                 : "=r"(r[0]), "=r"(r[1]), "=r"(r[2]), "=r"(r[3]) : "r"(addr));
}
__device__ __forceinline__ void ldmat_x4_t(uint32_t* r, uint32_t addr) {
    asm volatile("ldmatrix.sync.aligned.m8n8.x4.trans.shared.b16 {%0,%1,%2,%3}, [%4];"
                 : "=r"(r[0]), "=r"(r[1]), "=r"(r[2]), "=r"(r[3]) : "r"(addr));
}

__device__ __forceinline__ void mma_bf16(float* d, const uint32_t* a, const uint32_t* b) {
    asm volatile(
        "mma.sync.aligned.m16n8k16.row.col.f32.bf16.bf16.f32 "
        "{%0,%1,%2,%3}, {%4,%5,%6,%7}, {%8,%9}, {%0,%1,%2,%3};"
        : "+f"(d[0]), "+f"(d[1]), "+f"(d[2]), "+f"(d[3])
        : "r"(a[0]), "r"(a[1]), "r"(a[2]), "r"(a[3]), "r"(b[0]), "r"(b[1]));
}

// split two floats into bf16 hi pair + lo pair (packed u32)
__device__ __forceinline__ void split2(float a, float b, uint32_t& hi, uint32_t& lo) {
    __nv_bfloat16 ha = __float2bfloat16_rn(a);
    __nv_bfloat16 hb = __float2bfloat16_rn(b);
    __nv_bfloat162 h2 = __halves2bfloat162(ha, hb);
    hi = *(uint32_t*)&h2;
    __nv_bfloat162 l2 = __floats2bfloat162_rn(a - __bfloat162float(ha),
                                              b - __bfloat162float(hb));
    lo = *(uint32_t*)&l2;
}

// ================= bf16-split GEMM via mma.sync =================
// C[M,N] = A[M,K] @ Bt[N,K]^T + bias.
// Output: fp32 (Cf) or bf16 hi/lo pair (Chi/Clo).
#define G_BM 128
#define G_BN 128
#define G_BK 32
#define G_PAD 40
#define G_ARR_ELEMS (128 * G_PAD)
#define G_ARR_BYTES (G_ARR_ELEMS * 2)
#define G_STAGE_BYTES (4 * G_ARR_BYTES)
#define G_SMEM_BYTES (2 * G_STAGE_BYTES)

__global__ __launch_bounds__(256, 1)
void gemm_tc_kernel(const __nv_bfloat16* __restrict__ Ahi,
                    const __nv_bfloat16* __restrict__ Alo,
                    const __nv_bfloat16* __restrict__ Bhi,
                    const __nv_bfloat16* __restrict__ Blo,
                    const float* __restrict__ bias,
                    float* __restrict__ Cf,
                    __nv_bfloat16* __restrict__ Chi,
                    __nv_bfloat16* __restrict__ Clo,
                    int Kd, int Nd)
{
    extern __shared__ __align__(128) unsigned char dynsm[];
    const int tid = threadIdx.x;
    const int wid = tid >> 5;
    const int lane = tid & 31;
    const int wm = wid & 1;
    const int wn = wid >> 1;
    const int bm = blockIdx.y * G_BM;
    const int bn = blockIdx.x * G_BN;
    const int NK = Kd / G_BK;

    const uint32_t smem_base = smem_u32(dynsm);

    auto load_stage = [&](int st, int kt) {
        const int k0 = kt * G_BK;
        const uint32_t sb = smem_base + st * G_STAGE_BYTES;
#pragma unroll
        for (int i = tid; i < 2048; i += 256) {
            const int arr = i >> 9;
            const int t = i & 511;
            const int r = t >> 2;
            const int c = t & 3;
            const uint32_t soff = sb + arr * G_ARR_BYTES + r * (G_PAD * 2) + c * 16;
            const __nv_bfloat16* g;
            if (arr == 0)      g = Ahi + (size_t)(bm + r) * Kd + k0 + c * 8;
            else if (arr == 1) g = Alo + (size_t)(bm + r) * Kd + k0 + c * 8;
            else if (arr == 2) g = Bhi + (size_t)(bn + r) * Kd + k0 + c * 8;
            else               g = Blo + (size_t)(bn + r) * Kd + k0 + c * 8;
            cp_async16(soff, g);
        }
        CP_COMMIT();
    };

    float acc[4][4][4];
#pragma unroll
    for (int i = 0; i < 4; i++)
#pragma unroll
        for (int j = 0; j < 4; j++)
#pragma unroll
            for (int c = 0; c < 4; c++) acc[i][j][c] = 0.f;

    const int a_row_l = (lane & 15);
    const int a_k_l = (lane >> 4) * 8;
    const int b_row_l = (lane & 7) + (lane >> 4) * 8;
    const int b_k_l = ((lane >> 3) & 1) * 8;

    load_stage(0, 0);

    for (int kt = 0; kt < NK; kt++) {
        if (kt + 1 < NK) load_stage((kt + 1) & 1, kt + 1);
        else CP_COMMIT();
        cp_wait<1>();
        __syncthreads();

        const uint32_t sb = smem_base + (kt & 1) * G_STAGE_BYTES;
        const uint32_t aHiB = sb + 0 * G_ARR_BYTES;
        const uint32_t aLoB = sb + 1 * G_ARR_BYTES;
        const uint32_t bHiB = sb + 2 * G_ARR_BYTES;
        const uint32_t bLoB = sb + 3 * G_ARR_BYTES;

#pragma unroll
        for (int ks = 0; ks < 2; ks++) {
            const int kk = ks * 16;
            uint32_t ah[4][4], al[4][4], bh[2][4], bl[2][4];
#pragma unroll
            for (int i = 0; i < 4; i++) {
                const int row = wm * 64 + i * 16 + a_row_l;
                const uint32_t off = row * (G_PAD * 2) + (kk + a_k_l) * 2;
                ldmat_x4(ah[i], aHiB + off);
                ldmat_x4(al[i], aLoB + off);
            }
#pragma unroll
            for (int j = 0; j < 2; j++) {
                const int nrow = wn * 32 + j * 16 + b_row_l;
                const uint32_t off = nrow * (G_PAD * 2) + (kk + b_k_l) * 2;
                ldmat_x4(bh[j], bHiB + off);
                ldmat_x4(bl[j], bLoB + off);
            }
#pragma unroll
            for (int i = 0; i < 4; i++)
#pragma unroll
                for (int j = 0; j < 4; j++) {
                    const uint32_t* bfh = &bh[j >> 1][(j & 1) * 2];
                    const uint32_t* bfl = &bl[j >> 1][(j & 1) * 2];
                    mma_bf16(acc[i][j], ah[i], bfh);
                    mma_bf16(acc[i][j], ah[i], bfl);
                    mma_bf16(acc[i][j], al[i], bfh);
                }
        }
        __syncthreads();
    }

    // ---- epilogue: bias + store (fp32 OR bf16 hi/lo) ----
    const int qid = lane >> 2;
    const int tq = lane & 3;
#pragma unroll
    for (int j = 0; j < 4; j++) {
        const int col = bn + wn * 32 + j * 8 + tq * 2;
        const float b0 = __ldg(&bias[col]);
        const float b1 = __ldg(&bias[col + 1]);
#pragma unroll
        for (int i = 0; i < 4; i++) {
            const int r0 = bm + wm * 64 + i * 16 + qid;
            const float v0 = acc[i][j][0] + b0, v1 = acc[i][j][1] + b1;
            const float v2 = acc[i][j][2] + b0, v3 = acc[i][j][3] + b1;
            if (Cf) {
                *(float2*)&Cf[(size_t)r0 * Nd + col] = make_float2(v0, v1);
                *(float2*)&Cf[(size_t)(r0 + 8) * Nd + col] = make_float2(v2, v3);
            } else {
                uint32_t h, l;
                split2(v0, v1, h, l);
                *(uint32_t*)&Chi[(size_t)r0 * Nd + col] = h;
                *(uint32_t*)&Clo[(size_t)r0 * Nd + col] = l;
                split2(v2, v3, h, l);
                *(uint32_t*)&Chi[(size_t)(r0 + 8) * Nd + col] = h;
                *(uint32_t*)&Clo[(size_t)(r0 + 8) * Nd + col] = l;
            }
        }
    }
}

// ================= conversion kernels =================
__global__ __launch_bounds__(256) void split_kernel(
    const float* __restrict__ in, __nv_bfloat16* __restrict__ hi,
    __nv_bfloat16* __restrict__ lo, int n4)
{
    int i = blockIdx.x * blockDim.x + threadIdx.x;
    if (i >= n4) return;
    float4 v = ((const float4*)in)[i];
    uint32_t h0, l0, h1, l1;
    split2(v.x, v.y, h0, l0);
    split2(v.z, v.w, h1, l1);
    ((uint32_t*)hi)[i * 2 + 0] = h0;
    ((uint32_t*)hi)[i * 2 + 1] = h1;
    ((uint32_t*)lo)[i * 2 + 0] = l0;
    ((uint32_t*)lo)[i * 2 + 1] = l1;
}

__global__ __launch_bounds__(256) void transpose_split_kernel(
    const float* __restrict__ W, __nv_bfloat16* __restrict__ Th,
    __nv_bfloat16* __restrict__ Tl, int Kd, int Nd)
{
    __shared__ float t[32][33];
    const int k0 = blockIdx.y * 32;
    const int n0 = blockIdx.x * 32;
    const int tx = threadIdx.x;
    const int ty = threadIdx.y;
#pragma unroll
    for (int j = 0; j < 4; j++)
        t[ty + j * 8][tx] = W[(size_t)(k0 + ty + j * 8) * Nd + n0 + tx];
    __syncthreads();
#pragma unroll
    for (int j = 0; j < 4; j++) {
        int n = n0 + ty + j * 8;
        int k = k0 + tx;
        float v = t[tx][ty + j * 8];
        __nv_bfloat16 h = __float2bfloat16_rn(v);
        __nv_bfloat16 l = __float2bfloat16_rn(v - __bfloat162float(h));
        Th[(size_t)n * Kd + k] = h;
        Tl[(size_t)n * Kd + k] = l;
    }
}

// ================= tensor-core flash attention =================
// CTA: 128 q-rows x one head. 8 warps, each 16 q-rows.
// K/V streamed in 64-key tiles, double-buffered cp.async.
#define FL_STRIDE 136                        // padded bf16 per row (272B)
#define FL_Q_BYTES (128 * FL_STRIDE * 2)     // 34816
#define FL_ARR_BYTES (64 * FL_STRIDE * 2)    // 17408
#define FL_STAGE_BYTES (4 * FL_ARR_BYTES)    // 69632
#define FL_KV_OFF (2 * FL_Q_BYTES)
#define FL_MASK_OFF (FL_KV_OFF + 2 * FL_STAGE_BYTES)
#define FL_SMEM (FL_MASK_OFF + SS * 4)       // 217088

__global__ __launch_bounds__(256, 1)
void flash_tc_kernel(const __nv_bfloat16* __restrict__ Qhi,
                     const __nv_bfloat16* __restrict__ Qlo,
                     const __nv_bfloat16* __restrict__ Khi,
                     const __nv_bfloat16* __restrict__ Klo,
                     const __nv_bfloat16* __restrict__ Vhi,
                     const __nv_bfloat16* __restrict__ Vlo,
                     const float* __restrict__ mask,
                     __nv_bfloat16* __restrict__ Chi,
                     __nv_bfloat16* __restrict__ Clo)
{
    extern __shared__ __align__(128) unsigned char dynsm[];
    const uint32_t sbase = smem_u32(dynsm);
    const uint32_t qhiS = sbase;
    const uint32_t qloS = sbase + FL_Q_BYTES;
    const float* maskS = (const float*)(dynsm + FL_MASK_OFF);

    const int tid = threadIdx.x;
    const int w = tid >> 5;
    const int lane = tid & 31;
    const int b = blockIdx.z;
    const int h = blockIdx.y;
    const int q0 = blockIdx.x * 128;
    const size_t rb = (size_t)b * SS;          // global row base
    const int hc = h * HDD;                    // head col offset

    // ---- load Q (hi/lo) + mask ----
#pragma unroll
    for (int i = tid; i < 4096; i += 256) {
        const int arr = i >> 11;
        const int t = i & 2047;
        const int r = t >> 4;
        const int c = t & 15;
        const uint32_t soff = (arr ? qloS : qhiS) + r * (FL_STRIDE * 2) + c * 16;
        const __nv_bfloat16* g = (arr ? Qlo : Qhi) +
            (rb + q0 + r) * HH + hc + c * 8;
        cp_async16(soff, g);
    }
#pragma unroll
    for (int i = tid; i < 512; i += 256)
        cp_async16(sbase + FL_MASK_OFF + i * 16, mask + (size_t)b * SS + i * 4);

    auto load_kv = [&](int st, int kt) {
        const int k0 = kt * 64;
        const uint32_t sb = sbase + FL_KV_OFF + st * FL_STAGE_BYTES;
#pragma unroll
        for (int i = tid; i < 4096; i += 256) {
            const int arr = i >> 10;
            const int t = i & 1023;
            const int r = t >> 4;
            const int c = t & 15;
            const uint32_t soff = sb + arr * FL_ARR_BYTES + r * (FL_STRIDE * 2) + c * 16;
            const __nv_bfloat16* g;
            const size_t go = (rb + k0 + r) * HH + hc + c * 8;
            if (arr == 0)      g = Khi + go;
            else if (arr == 1) g = Klo + go;
            else if (arr == 2) g = Vhi + go;
            else               g = Vlo + go;
            cp_async16(soff, g);
        }
        CP_COMMIT();
    };

    load_kv(0, 0);   // group 0 also contains Q + mask

    const float sc2 = 0.08838834764831845f * 1.4426950408889634f; // scale*log2e
    const float L2E = 1.4426950408889634f;

    float o[16][4];
#pragma unroll
    for (int t = 0; t < 16; t++)
#pragma unroll
        for (int c = 0; c < 4; c++) o[t][c] = 0.f;
    float m0 = -1e30f, m1 = -1e30f, l0 = 0.f, l1 = 0.f;

    const int a_row_l = (lane & 15);
    const int a_k_l = (lane >> 4) * 8;
    const int b_row_l = (lane & 7) + (lane >> 4) * 8;
    const int b_k_l = ((lane >> 3) & 1) * 8;
    const int v_row_l = (lane & 7) + ((lane >> 3) & 1) * 8;
    const int v_col_l = (lane >> 4) * 8;
    const int tq2 = (lane & 3) * 2;

    __syncthreads();   // smem visible (loads are async; waits below)

    for (int kt = 0; kt < SS / 64; kt++) {
        if (kt + 1 < SS / 64) load_kv((kt + 1) & 1, kt + 1);
        else CP_COMMIT();
        cp_wait<1>();
        __syncthreads();

        const uint32_t sb = sbase + FL_KV_OFF + (kt & 1) * FL_STAGE_BYTES;
        const uint32_t kHiB = sb + 0 * FL_ARR_BYTES;
        const uint32_t kLoB = sb + 1 * FL_ARR_BYTES;
        const uint32_t vHiB = sb + 2 * FL_ARR_BYTES;
        const uint32_t vLoB = sb + 3 * FL_ARR_BYTES;

        // ---- S = Q K^T  (8 n8-tiles of 8 keys) ----
        float s[8][4];
#pragma unroll
        for (int j = 0; j < 8; j++)
#pragma unroll
            for (int c = 0; c < 4; c++) s[j][c] = 0.f;

#pragma unroll
        for (int ks = 0; ks < 8; ks++) {
            uint32_t qh[4], ql[4];
            const uint32_t qoff = (w * 16 + a_row_l) * (FL_STRIDE * 2) +
                                  (ks * 16 + a_k_l) * 2;
            ldmat_x4(qh, qhiS + qoff);
            ldmat_x4(ql, qloS + qoff);
#pragma unroll
            for (int j = 0; j < 4; j++) {
                uint32_t kh[4], kl[4];
                const uint32_t koff = (j * 16 + b_row_l) * (FL_STRIDE * 2) +
                                      (ks * 16 + b_k_l) * 2;
                ldmat_x4(kh, kHiB + koff);
                ldmat_x4(kl, kLoB + koff);
                mma_bf16(s[2 * j], qh, &kh[0]);
                mma_bf16(s[2 * j], qh, &kl[0]);
                mma_bf16(s[2 * j], ql, &kh[0]);
                mma_bf16(s[2 * j + 1], qh, &kh[2]);
                mma_bf16(s[2 * j + 1], qh, &kl[2]);
                mma_bf16(s[2 * j + 1], ql, &kh[2]);
            }
        }

        // ---- scale + mask (exp2 domain) ----
#pragma unroll
        for (int j = 0; j < 8; j++) {
            const float mk0 = maskS[kt * 64 + j * 8 + tq2] * L2E;
            const float mk1 = maskS[kt * 64 + j * 8 + tq2 + 1] * L2E;
            s[j][0] = fmaf(s[j][0], sc2, mk0);
            s[j][1] = fmaf(s[j][1], sc2, mk1);
            s[j][2] = fmaf(s[j][2], sc2, mk0);
            s[j][3] = fmaf(s[j][3], sc2, mk1);
        }

        // ---- online softmax ----
        float rm0 = -1e30f, rm1 = -1e30f;
#pragma unroll
        for (int j = 0; j < 8; j++) {
            rm0 = fmaxf(rm0, fmaxf(s[j][0], s[j][1]));
            rm1 = fmaxf(rm1, fmaxf(s[j][2], s[j][3]));
        }
        rm0 = fmaxf(rm0, __shfl_xor_sync(0xffffffffu, rm0, 1));
        rm0 = fmaxf(rm0, __shfl_xor_sync(0xffffffffu, rm0, 2));
        rm1 = fmaxf(rm1, __shfl_xor_sync(0xffffffffu, rm1, 1));
        rm1 = fmaxf(rm1, __shfl_xor_sync(0xffffffffu, rm1, 2));
        const float nm0 = fmaxf(m0, rm0), nm1 = fmaxf(m1, rm1);
        const float corr0 = exp2f(m0 - nm0), corr1 = exp2f(m1 - nm1);
        float sum0 = 0.f, sum1 = 0.f;
#pragma unroll
        for (int j = 0; j < 8; j++) {
            s[j][0] = exp2f(s[j][0] - nm0);
            s[j][1] = exp2f(s[j][1] - nm0);
            s[j][2] = exp2f(s[j][2] - nm1);
            s[j][3] = exp2f(s[j][3] - nm1);
            sum0 += s[j][0] + s[j][1];
            sum1 += s[j][2] + s[j][3];
        }
        sum0 += __shfl_xor_sync(0xffffffffu, sum0, 1);
        sum0 += __shfl_xor_sync(0xffffffffu, sum0, 2);
        sum1 += __shfl_xor_sync(0xffffffffu, sum1, 1);
        sum1 += __shfl_xor_sync(0xffffffffu, sum1, 2);
        l0 = l0 * corr0 + sum0;
        l1 = l1 * corr1 + sum1;
        m0 = nm0; m1 = nm1;
#pragma unroll
        for (int t = 0; t < 16; t++) {
            o[t][0] *= corr0; o[t][1] *= corr0;
            o[t][2] *= corr1; o[t][3] *= corr1;
        }

        // ---- O += P V ----
#pragma unroll
        for (int ks = 0; ks < 4; ks++) {
            uint32_t ahi[4], alo[4];
            split2(s[2 * ks][0], s[2 * ks][1], ahi[0], alo[0]);
            split2(s[2 * ks][2], s[2 * ks][3], ahi[1], alo[1]);
            split2(s[2 * ks + 1][0], s[2 * ks + 1][1], ahi[2], alo[2]);
            split2(s[2 * ks + 1][2], s[2 * ks + 1][3], ahi[3], alo[3]);
#pragma unroll
            for (int j = 0; j < 8; j++) {
                uint32_t vh[4], vl[4];
                const uint32_t voff = (ks * 16 + v_row_l) * (FL_STRIDE * 2) +
                                      (j * 16 + v_col_l) * 2;
                ldmat_x4_t(vh, vHiB + voff);
                ldmat_x4_t(vl, vLoB + voff);
                mma_bf16(o[2 * j], ahi, &vh[0]);
                mma_bf16(o[2 * j], ahi, &vl[0]);
                mma_bf16(o[2 * j], alo, &vh[0]);
                mma_bf16(o[2 * j + 1], ahi, &vh[2]);
                mma_bf16(o[2 * j + 1], ahi, &vl[2]);
                mma_bf16(o[2 * j + 1], alo, &vh[2]);
            }
        }
        __syncthreads();
    }

    // ---- normalize + write ctx (bf16 hi/lo) ----
    const float inv0 = 1.f / l0, inv1 = 1.f / l1;
    const int g = lane >> 2;
    const size_t row0 = rb + q0 + w * 16 + g;
    const size_t row1 = row0 + 8;
#pragma unroll
    for (int t = 0; t < 16; t++) {
        const int col = hc + t * 8 + tq2;
        uint32_t hi, lo;
        split2(o[t][0] * inv0, o[t][1] * inv0, hi, lo);
        *(uint32_t*)&Chi[row0 * HH + col] = hi;
        *(uint32_t*)&Clo[row0 * HH + col] = lo;
        split2(o[t][2] * inv1, o[t][3] * inv1, hi, lo);
        *(uint32_t*)&Chi[row1 * HH + col] = hi;
        *(uint32_t*)&Clo[row1 * HH + col] = lo;
    }
}

// ---------------- launch ----------------
extern "C" void kernel_launch(void* const* d_in, const int* in_sizes, int n_in,
                              void* d_out, int out_size)
{
    (void)in_sizes; (void)n_in; (void)out_size;
    const float* x    = (const float*)d_in[0];
    const float* mask = (const float*)d_in[1];
    const float* Wq   = (const float*)d_in[2];
    const float* bq   = (const float*)d_in[3];
    const float* Wk   = (const float*)d_in[4];
    const float* bk   = (const float*)d_in[5];
    const float* Wv   = (const float*)d_in[6];
    const float* bv   = (const float*)d_in[7];
    const float* Wo   = (const float*)d_in[8];
    const float* bo   = (const float*)d_in[9];
    float* out = (float*)d_out;

    __nv_bfloat16 *qhi, *qlo, *khi, *klo, *vhi, *vlo, *xhi, *xlo, *wthi, *wtlo;
    cudaGetSymbolAddress((void**)&qhi, g_Qhi);
    cudaGetSymbolAddress((void**)&qlo, g_Qlo);
    cudaGetSymbolAddress((void**)&khi, g_Khi);
    cudaGetSymbolAddress((void**)&klo, g_Klo);
    cudaGetSymbolAddress((void**)&vhi, g_Vhi);
    cudaGetSymbolAddress((void**)&vlo, g_Vlo);
    cudaGetSymbolAddress((void**)&xhi, g_xhi);
    cudaGetSymbolAddress((void**)&xlo, g_xlo);
    cudaGetSymbolAddress((void**)&wthi, g_wthi);
    cudaGetSymbolAddress((void**)&wtlo, g_wtlo);

    cudaFuncSetAttribute(gemm_tc_kernel,
                         cudaFuncAttributeMaxDynamicSharedMemorySize, G_SMEM_BYTES);
    cudaFuncSetAttribute(flash_tc_kernel,
                         cudaFuncAttributeMaxDynamicSharedMemorySize, FL_SMEM);

    const int n4 = (MROWS * HH) / 4;
    dim3 tgrid(HH / 32, HH / 32);
    dim3 tblk(32, 8);
    dim3 ggrid(HH / G_BN, MROWS / G_BM);

    // split x once
    split_kernel<<<(n4 + 255) / 256, 256>>>(x, xhi, xlo, n4);

    // Q, K, V projections -> bf16 hi/lo directly
    transpose_split_kernel<<<tgrid, tblk>>>(Wq, wthi, wtlo, HH, HH);
    gemm_tc_kernel<<<ggrid, 256, G_SMEM_BYTES>>>(xhi, xlo, wthi, wtlo, bq,
                                                 nullptr, qhi, qlo, HH, HH);
    transpose_split_kernel<<<tgrid, tblk>>>(Wk, wthi, wtlo, HH, HH);
    gemm_tc_kernel<<<ggrid, 256, G_SMEM_BYTES>>>(xhi, xlo, wthi, wtlo, bk,
                                                 nullptr, khi, klo, HH, HH);
    transpose_split_kernel<<<tgrid, tblk>>>(Wv, wthi, wtlo, HH, HH);
    gemm_tc_kernel<<<ggrid, 256, G_SMEM_BYTES>>>(xhi, xlo, wthi, wtlo, bv,
                                                 nullptr, vhi, vlo, HH, HH);

    // attention (writes ctx hi/lo into xhi/xlo, which are free now)
    flash_tc_kernel<<<dim3(SS / 128, NHH, BB), 256, FL_SMEM>>>(
        qhi, qlo, khi, klo, vhi, vlo, mask, xhi, xlo);

    // output projection -> fp32 out
    transpose_split_kernel<<<tgrid, tblk>>>(Wo, wthi, wtlo, HH, HH);
    gemm_tc_kernel<<<ggrid, 256, G_SMEM_BYTES>>>(xhi, xlo, wthi, wtlo, bo,
                                                 out, nullptr, nullptr, HH, HH);
}